// round 2
// baseline (speedup 1.0000x reference)
#include <cuda_runtime.h>
#include <math.h>

#define BB 256
#define HH 28
#define WW 28
// padded 30x30, channels 32/32/64

// Scratch (device globals: allocation-free rule)
__device__ float g_h1p[BB*30*30*32];   // conv1 out, NHWC padded, zero border
__device__ float g_offs[BB*28*28*18];  // p_conv offsets, NHWC
__device__ float g_h2p[BB*30*30*32];   // deform out, NHWC padded, zero border
__device__ float g_part[BB*14*64];     // partial pooled sums of relu(conv3)

// ---------------------------------------------------------------------------
// K1: conv1(3->32, pad1) + relu + bn1  -> g_h1p (NHWC padded, zero borders)
// warp per padded pixel, lane = out channel
// ---------------------------------------------------------------------------
__global__ void k1_conv1(const float* __restrict__ x, const float* __restrict__ w1,
                         const float* __restrict__ g1, const float* __restrict__ b1,
                         const float* __restrict__ m1, const float* __restrict__ v1) {
    __shared__ float ws[27*32];          // [c*9+tap][o]
    int tid = threadIdx.x;
    for (int i = tid; i < 27*32; i += blockDim.x) {
        int tap = i >> 5, o = i & 31;
        ws[i] = w1[o*27 + tap];
    }
    __syncthreads();
    int wg   = blockIdx.x*8 + (tid >> 5);
    int lane = tid & 31;
    int b = wg / 900, rem = wg % 900;
    int yp = rem / 30, xp = rem % 30;
    float* dst = &g_h1p[((b*30+yp)*30+xp)*32 + lane];
    if (yp == 0 || yp == 29 || xp == 0 || xp == 29) { *dst = 0.f; return; }
    int y = yp - 1, x0 = xp - 1;
    float acc = 0.f;
    #pragma unroll
    for (int c = 0; c < 3; c++) {
        #pragma unroll
        for (int ky = 0; ky < 3; ky++) {
            int iy = y + ky - 1;
            #pragma unroll
            for (int kx = 0; kx < 3; kx++) {
                int ix = x0 + kx - 1;
                float xv = 0.f;
                if (iy >= 0 && iy < 28 && ix >= 0 && ix < 28)
                    xv = __ldg(&x[((b*3+c)*28+iy)*28+ix]);
                acc = fmaf(xv, ws[(c*9+ky*3+kx)*32 + lane], acc);
            }
        }
    }
    acc = fmaxf(acc, 0.f);
    float inv = g1[lane] * rsqrtf(v1[lane] + 1e-5f);
    *dst = acc * inv + (b1[lane] - m1[lane]*inv);
}

// ---------------------------------------------------------------------------
// K2: p_conv(32->18, pad1) + bias -> g_offs
// warp per pixel; lanes 0..17 = offset channels
// ---------------------------------------------------------------------------
__global__ void k2_pconv(const float* __restrict__ wp, const float* __restrict__ bp) {
    __shared__ float ws[288*18];         // [c*9+tap][o]
    int tid = threadIdx.x;
    for (int i = tid; i < 288*18; i += blockDim.x) {
        int tc = i / 18, o = i % 18;
        ws[i] = wp[o*288 + tc];
    }
    __syncthreads();
    int wg   = blockIdx.x*8 + (tid >> 5);
    int lane = tid & 31;
    int b = wg / 784, rem = wg % 784;
    int y = rem / 28, x0 = rem % 28;
    if (lane >= 18) return;
    const float* srcp = &g_h1p[((b*30+y)*30+x0)*32];  // padded window origin
    float acc = 0.f;
    for (int c = 0; c < 32; c++) {
        #pragma unroll
        for (int t = 0; t < 9; t++) {
            float xv = srcp[((t/3)*30 + (t%3))*32 + c];
            acc = fmaf(xv, ws[(c*9+t)*18 + lane], acc);
        }
    }
    g_offs[((b*28+y)*28+x0)*18 + lane] = acc + bp[lane];
}

// ---------------------------------------------------------------------------
// K3: deformable sample (bilinear, v2 clip semantics) + 9-pt conv (32->32)
//     + relu + bn2 -> g_h2p (NHWC padded, zero borders)
// warp per padded pixel; phase A lane=in-channel, phase B lane=out-channel
// ---------------------------------------------------------------------------
__global__ void k3_deform(const float* __restrict__ w2, const float* __restrict__ g2,
                          const float* __restrict__ b2_, const float* __restrict__ m2,
                          const float* __restrict__ v2) {
    __shared__ float ws[288*32];         // [(c*9+n)][o]
    int tid = threadIdx.x;
    for (int i = tid; i < 288*32; i += blockDim.x) {
        int cn = i >> 5, o = i & 31;
        ws[i] = w2[o*288 + cn];
    }
    __syncthreads();
    int wg   = blockIdx.x*8 + (tid >> 5);
    int lane = tid & 31;
    int b = wg / 900, rem = wg % 900;
    int yp = rem / 30, xp = rem % 30;
    float* dst = &g_h2p[((b*30+yp)*30+xp)*32 + lane];
    if (yp == 0 || yp == 29 || xp == 0 || xp == 29) { *dst = 0.f; return; }
    int y = yp - 1, x0 = xp - 1;
    const float* img  = &g_h1p[b*900*32];
    const float* offp = &g_offs[((b*28+y)*28+x0)*18];

    float xoff[9];
    #pragma unroll
    for (int n = 0; n < 9; n++) {
        float oy = offp[n];
        float ox = offp[9+n];
        float pyr = (float)(y + n/3) + oy;       // (y+1) + (n/3 - 1)
        float pxr = (float)(x0 + n%3) + ox;
        float fy = floorf(pyr), fx = floorf(pxr);
        float qy0 = fminf(fmaxf(fy,      0.f), 29.f);
        float qy1 = fminf(fmaxf(fy + 1.f,0.f), 29.f);
        float qx0 = fminf(fmaxf(fx,      0.f), 29.f);
        float qx1 = fminf(fmaxf(fx + 1.f,0.f), 29.f);
        float pyc = fminf(fmaxf(pyr, 0.f), 29.f);
        float pxc = fminf(fmaxf(pxr, 0.f), 29.f);
        float glt = (1.f + (qy0 - pyc)) * (1.f + (qx0 - pxc));
        float grb = (1.f - (qy1 - pyc)) * (1.f - (qx1 - pxc));
        float glb = (1.f + (qy0 - pyc)) * (1.f - (qx1 - pxc));
        float grt = (1.f - (qy1 - pyc)) * (1.f + (qx0 - pxc));
        int iy0 = (int)qy0, iy1 = (int)qy1, ix0 = (int)qx0, ix1 = (int)qx1;
        float v00 = img[(iy0*30+ix0)*32 + lane];
        float v11 = img[(iy1*30+ix1)*32 + lane];
        float v01 = img[(iy0*30+ix1)*32 + lane];
        float v10 = img[(iy1*30+ix0)*32 + lane];
        xoff[n] = glt*v00 + grb*v11 + glb*v01 + grt*v10;
    }

    float acc = 0.f;
    #pragma unroll
    for (int n = 0; n < 9; n++) {
        #pragma unroll
        for (int c = 0; c < 32; c++) {
            float v = __shfl_sync(0xffffffffu, xoff[n], c);
            acc = fmaf(v, ws[(c*9+n)*32 + lane], acc);
        }
    }
    acc = fmaxf(acc, 0.f);
    float inv = g2[lane] * rsqrtf(v2[lane] + 1e-5f);
    *dst = acc * inv + (b2_[lane] - m2[lane]*inv);
}

// ---------------------------------------------------------------------------
// K4: conv3(32->64, pad1) + relu + partial spatial sum (bn folded into head)
// block = (image, 2-row strip); warp per pixel-group of 7; lane = o - obase
// ---------------------------------------------------------------------------
__global__ void k4_conv3(const float* __restrict__ w3, int obase) {
    __shared__ float ws[288*32];         // [(c*9+tap)][o]
    __shared__ float red[32];
    int tid = threadIdx.x;
    for (int i = tid; i < 288*32; i += blockDim.x) {
        int tc = i >> 5, o = i & 31;
        ws[i] = w3[(obase + o)*288 + tc];
    }
    if (tid < 32) red[tid] = 0.f;
    __syncthreads();
    int b = blockIdx.x / 14;
    int strip = blockIdx.x % 14;
    int warp = tid >> 5, lane = tid & 31;
    const float* img = &g_h2p[b*900*32];
    float s = 0.f;
    for (int i = 0; i < 7; i++) {
        int p = warp*7 + i;
        int y = strip*2 + p/28, x0 = p%28;
        const float* srcp = &img[(y*30+x0)*32];
        float acc = 0.f;
        for (int c = 0; c < 32; c++) {
            #pragma unroll
            for (int t = 0; t < 9; t++) {
                float xv = srcp[((t/3)*30 + (t%3))*32 + c];
                acc = fmaf(xv, ws[(c*9+t)*32 + lane], acc);
            }
        }
        s += fmaxf(acc, 0.f);
    }
    atomicAdd(&red[lane], s);
    __syncthreads();
    if (tid < 32) g_part[(b*14+strip)*64 + obase + tid] = red[tid];
}

// ---------------------------------------------------------------------------
// K5: reduce partials -> mean -> bn3 -> linear(64->10) -> log_softmax
// ---------------------------------------------------------------------------
__global__ void k5_head(const float* __restrict__ g3, const float* __restrict__ b3,
                        const float* __restrict__ m3, const float* __restrict__ v3,
                        const float* __restrict__ wc, const float* __restrict__ bc,
                        float* __restrict__ out) {
    __shared__ float hsh[64];
    __shared__ float lg[10];
    int b = blockIdx.x, tid = threadIdx.x;
    if (tid < 64) {
        float s = 0.f;
        for (int k = 0; k < 14; k++) s += g_part[(b*14+k)*64 + tid];
        s *= (1.f/784.f);
        float inv = g3[tid] * rsqrtf(v3[tid] + 1e-5f);
        hsh[tid] = s * inv + (b3[tid] - m3[tid]*inv);
    }
    __syncthreads();
    if (tid < 10) {
        float acc = bc[tid];
        for (int o = 0; o < 64; o++) acc = fmaf(hsh[o], wc[tid*64 + o], acc);
        lg[tid] = acc;
    }
    __syncthreads();
    if (tid < 10) {
        float mx = -1e30f;
        for (int j = 0; j < 10; j++) mx = fmaxf(mx, lg[j]);
        float se = 0.f;
        for (int j = 0; j < 10; j++) se += expf(lg[j] - mx);
        out[b*10 + tid] = lg[tid] - mx - logf(se);
    }
}

// ---------------------------------------------------------------------------
extern "C" void kernel_launch(void* const* d_in, const int* in_sizes, int n_in,
                              void* d_out, int out_size) {
    const float* x  = (const float*)d_in[0];
    const float* w1 = (const float*)d_in[1];
    const float* g1 = (const float*)d_in[2];
    const float* b1 = (const float*)d_in[3];
    const float* m1 = (const float*)d_in[4];
    const float* v1 = (const float*)d_in[5];
    const float* wp = (const float*)d_in[6];
    const float* bp = (const float*)d_in[7];
    const float* w2 = (const float*)d_in[8];
    const float* g2 = (const float*)d_in[9];
    const float* b2 = (const float*)d_in[10];
    const float* m2 = (const float*)d_in[11];
    const float* v2 = (const float*)d_in[12];
    const float* w3 = (const float*)d_in[13];
    const float* g3 = (const float*)d_in[14];
    const float* b3 = (const float*)d_in[15];
    const float* m3 = (const float*)d_in[16];
    const float* v3 = (const float*)d_in[17];
    const float* wc = (const float*)d_in[18];
    const float* bc = (const float*)d_in[19];

    // 256*30*30 padded pixels, 1 warp each, 8 warps/block
    k1_conv1<<<28800, 256>>>(x, w1, g1, b1, m1, v1);
    // 256*28*28 pixels, 1 warp each
    k2_pconv<<<25088, 256>>>(wp, bp);
    k3_deform<<<28800, 256>>>(w2, g2, b2, m2, v2);
    // 256 images * 14 strips, two o-halves
    k4_conv3<<<3584, 256>>>(w3, 0);
    k4_conv3<<<3584, 256>>>(w3, 32);
    k5_head<<<256, 64>>>(g3, b3, m3, v3, wc, bc, (float*)d_out);
}

// round 3
// speedup vs baseline: 3.1086x; 3.1086x over previous
#include <cuda_runtime.h>
#include <math.h>

#define BB 256
#define HH 28
#define WW 28

// Scratch (device globals: allocation-free rule). Zero-initialized at module
// load; g_h2p borders are never written by any kernel -> stay zero (padding).
__device__ float g_h1p[BB*30*30*32];   // conv1 out, NHWC padded, zero border
__device__ float g_offs[BB*28*28*18];  // p_conv offsets, NHWC
__device__ float g_h2p[BB*30*30*32];   // deform out, NHWC padded, zero border
__device__ float g_part[BB*7*64];      // partial pooled sums of relu(conv3)

// ---------------------------------------------------------------------------
// K1: conv1(3->32, pad1) + relu + bn1  -> g_h1p (NHWC padded, zero borders)
// warp per padded pixel, lane = out channel  (small kernel, unchanged)
// ---------------------------------------------------------------------------
__global__ void k1_conv1(const float* __restrict__ x, const float* __restrict__ w1,
                         const float* __restrict__ g1, const float* __restrict__ b1,
                         const float* __restrict__ m1, const float* __restrict__ v1) {
    __shared__ float ws[27*32];          // [c*9+tap][o]
    int tid = threadIdx.x;
    for (int i = tid; i < 27*32; i += blockDim.x) {
        int tap = i >> 5, o = i & 31;
        ws[i] = w1[o*27 + tap];
    }
    __syncthreads();
    int wg   = blockIdx.x*8 + (tid >> 5);
    int lane = tid & 31;
    int b = wg / 900, rem = wg % 900;
    int yp = rem / 30, xp = rem % 30;
    float* dst = &g_h1p[((b*30+yp)*30+xp)*32 + lane];
    if (yp == 0 || yp == 29 || xp == 0 || xp == 29) { *dst = 0.f; return; }
    int y = yp - 1, x0 = xp - 1;
    float acc = 0.f;
    #pragma unroll
    for (int c = 0; c < 3; c++) {
        #pragma unroll
        for (int ky = 0; ky < 3; ky++) {
            int iy = y + ky - 1;
            #pragma unroll
            for (int kx = 0; kx < 3; kx++) {
                int ix = x0 + kx - 1;
                float xv = 0.f;
                if (iy >= 0 && iy < 28 && ix >= 0 && ix < 28)
                    xv = __ldg(&x[((b*3+c)*28+iy)*28+ix]);
                acc = fmaf(xv, ws[(c*9+ky*3+kx)*32 + lane], acc);
            }
        }
    }
    acc = fmaxf(acc, 0.f);
    float inv = g1[lane] * rsqrtf(v1[lane] + 1e-5f);
    *dst = acc * inv + (b1[lane] - m1[lane]*inv);
}

// ---------------------------------------------------------------------------
// K2: p_conv(32->18, pad1) + bias -> g_offs
// block = (image, 4-row strip). Acts staged in shared, weights padded to 32.
// warp = output row; 7-pixel register tile; lane = o (0..17 live).
// dyn smem: wsh 288*32 floats (36864B) + ash 6*30*32 floats (23040B) = 59904B
// ---------------------------------------------------------------------------
__global__ void k2_pconv(const float* __restrict__ wp, const float* __restrict__ bp) {
    extern __shared__ float sm2[];
    float* wsh = sm2;                 // [(c*9+t)*32 + o]
    float* ash = sm2 + 288*32;        // [ry][x][c], 6x30x32
    int tid = threadIdx.x;
    int b = blockIdx.x / 7, strip = blockIdx.x % 7;
    for (int i = tid; i < 288*32; i += 128) {
        int cn = i >> 5, o = i & 31;
        wsh[i] = (o < 18) ? wp[o*288 + cn] : 0.f;
    }
    const float* src = &g_h1p[(b*30 + strip*4)*30*32];
    for (int i = tid; i < 6*30*32; i += 128) ash[i] = src[i];
    __syncthreads();

    int warp = tid >> 5, lane = tid & 31;
    int y = strip*4 + warp;           // output row
    float bpv = (lane < 18) ? bp[lane] : 0.f;
    for (int x0 = 0; x0 < 28; x0 += 7) {
        float acc[7] = {0,0,0,0,0,0,0};
        for (int c = 0; c < 32; c++) {
            #pragma unroll
            for (int t = 0; t < 9; t++) {
                float w = wsh[(c*9+t)*32 + lane];
                const float* ap = &ash[((warp + t/3)*30 + x0 + (t%3))*32 + c];
                #pragma unroll
                for (int i = 0; i < 7; i++)
                    acc[i] = fmaf(ap[i*32], w, acc[i]);
            }
        }
        if (lane < 18) {
            #pragma unroll
            for (int i = 0; i < 7; i++)
                g_offs[((b*28+y)*28 + x0 + i)*18 + lane] = acc[i] + bpv;
        }
    }
}

// ---------------------------------------------------------------------------
// K3: fused deformable sample + 9pt conv (32->32) + relu + bn2 -> g_h2p
// block = (image, 2-row strip of 56 px), 256 threads.
// Phase A: 8 warps sample 7 px each (lane = in channel) -> xsh[56][288]
// Phase B: 8 warps, 7-px register tile (lane = out channel)
// dyn smem: wsh 9216 floats (36864B) + xsh 56*288 floats (64512B) = 101376B
// ---------------------------------------------------------------------------
__global__ void k3_deform(const float* __restrict__ w2, const float* __restrict__ g2,
                          const float* __restrict__ b2_, const float* __restrict__ m2,
                          const float* __restrict__ v2) {
    extern __shared__ float sm3[];
    float* wsh = sm3;                 // [(n*32+c)*32 + o]
    float* xsh = sm3 + 9216;          // [pl*288 + n*32 + c]
    int tid = threadIdx.x;
    int b = blockIdx.x / 14, strip = blockIdx.x % 14;
    int y0 = strip*2;
    for (int i = tid; i < 9216; i += 256) {
        int nc = i >> 5, o = i & 31;
        int c = nc & 31, n = nc >> 5;
        wsh[i] = w2[o*288 + c*9 + n];
    }
    int warp = tid >> 5, lane = tid & 31;
    const float* img = &g_h1p[b*900*32];

    // Phase A: sampling
    for (int k = 0; k < 7; k++) {
        int pl = warp + k*8;          // 0..55
        int y = y0 + pl/28, x = pl%28;
        const float* offp = &g_offs[((b*28+y)*28+x)*18];
        #pragma unroll
        for (int n = 0; n < 9; n++) {
            float oy = offp[n];
            float ox = offp[9+n];
            float pyr = (float)(y + n/3) + oy;
            float pxr = (float)(x + n%3) + ox;
            float fy = floorf(pyr), fx = floorf(pxr);
            float qy0 = fminf(fmaxf(fy,       0.f), 29.f);
            float qy1 = fminf(fmaxf(fy + 1.f, 0.f), 29.f);
            float qx0 = fminf(fmaxf(fx,       0.f), 29.f);
            float qx1 = fminf(fmaxf(fx + 1.f, 0.f), 29.f);
            float pyc = fminf(fmaxf(pyr, 0.f), 29.f);
            float pxc = fminf(fmaxf(pxr, 0.f), 29.f);
            float glt = (1.f + (qy0 - pyc)) * (1.f + (qx0 - pxc));
            float grb = (1.f - (qy1 - pyc)) * (1.f - (qx1 - pxc));
            float glb = (1.f + (qy0 - pyc)) * (1.f - (qx1 - pxc));
            float grt = (1.f - (qy1 - pyc)) * (1.f + (qx0 - pxc));
            int iy0 = (int)qy0, iy1 = (int)qy1, ix0 = (int)qx0, ix1 = (int)qx1;
            float v00 = img[(iy0*30+ix0)*32 + lane];
            float v11 = img[(iy1*30+ix1)*32 + lane];
            float v01 = img[(iy0*30+ix1)*32 + lane];
            float v10 = img[(iy1*30+ix0)*32 + lane];
            xsh[pl*288 + n*32 + lane] = glt*v00 + grb*v11 + glb*v01 + grt*v10;
        }
    }
    __syncthreads();

    // Phase B: 288 -> 32 GEMM, 7-px tile per warp
    int pbase = warp*7;
    float acc[7] = {0,0,0,0,0,0,0};
    const float* xp0 = &xsh[pbase*288];
    for (int nc = 0; nc < 288; nc++) {
        float w = wsh[nc*32 + lane];
        #pragma unroll
        for (int i = 0; i < 7; i++)
            acc[i] = fmaf(xp0[i*288 + nc], w, acc[i]);
    }
    float inv = g2[lane] * rsqrtf(v2[lane] + 1e-5f);
    float sh  = b2_[lane] - m2[lane]*inv;
    #pragma unroll
    for (int i = 0; i < 7; i++) {
        int px = pbase + i;
        int y = y0 + px/28, x = px%28;
        g_h2p[((b*30+y+1)*30 + x+1)*32 + lane] = fmaxf(acc[i], 0.f)*inv + sh;
    }
}

// ---------------------------------------------------------------------------
// K4: conv3(32->64, pad1) + relu + partial spatial sum (bn folded into head)
// block = (image, 4-row strip), 128 threads. All 64 outputs per block
// (float2 weights: o=lane and o=lane+32). 7-px x 2-o register tile.
// dyn smem: wsh 288*32 float2 (73728B) + ash 6*30*32 floats (23040B) = 96768B
// ---------------------------------------------------------------------------
__global__ void k4_conv3(const float* __restrict__ w3) {
    extern __shared__ float sm4[];
    float2* wsh = (float2*)sm4;       // [(c*9+t)*32 + lane] -> (w[o=lane], w[o=lane+32])
    float*  ash = sm4 + 2*288*32;     // [ry][x][c], 6x30x32
    __shared__ float red[64];
    int tid = threadIdx.x;
    int b = blockIdx.x / 7, strip = blockIdx.x % 7;
    for (int i = tid; i < 288*32; i += 128) {
        int cn = i >> 5, l = i & 31;
        wsh[i] = make_float2(w3[l*288 + cn], w3[(l+32)*288 + cn]);
    }
    const float* src = &g_h2p[(b*30 + strip*4)*30*32];
    for (int i = tid; i < 6*30*32; i += 128) ash[i] = src[i];
    if (tid < 64) red[tid] = 0.f;
    __syncthreads();

    int warp = tid >> 5, lane = tid & 31;
    float s0 = 0.f, s1 = 0.f;
    for (int x0 = 0; x0 < 28; x0 += 7) {
        float a0[7] = {0,0,0,0,0,0,0};
        float a1[7] = {0,0,0,0,0,0,0};
        for (int c = 0; c < 32; c++) {
            #pragma unroll
            for (int t = 0; t < 9; t++) {
                float2 w = wsh[(c*9+t)*32 + lane];
                const float* ap = &ash[((warp + t/3)*30 + x0 + (t%3))*32 + c];
                #pragma unroll
                for (int i = 0; i < 7; i++) {
                    float a = ap[i*32];
                    a0[i] = fmaf(a, w.x, a0[i]);
                    a1[i] = fmaf(a, w.y, a1[i]);
                }
            }
        }
        #pragma unroll
        for (int i = 0; i < 7; i++) {
            s0 += fmaxf(a0[i], 0.f);
            s1 += fmaxf(a1[i], 0.f);
        }
    }
    atomicAdd(&red[lane],      s0);
    atomicAdd(&red[lane + 32], s1);
    __syncthreads();
    if (tid < 64) g_part[(b*7+strip)*64 + tid] = red[tid];
}

// ---------------------------------------------------------------------------
// K5: reduce partials -> mean -> bn3 -> linear(64->10) -> log_softmax
// ---------------------------------------------------------------------------
__global__ void k5_head(const float* __restrict__ g3, const float* __restrict__ b3,
                        const float* __restrict__ m3, const float* __restrict__ v3,
                        const float* __restrict__ wc, const float* __restrict__ bc,
                        float* __restrict__ out) {
    __shared__ float hsh[64];
    __shared__ float lg[10];
    int b = blockIdx.x, tid = threadIdx.x;
    if (tid < 64) {
        float s = 0.f;
        for (int k = 0; k < 7; k++) s += g_part[(b*7+k)*64 + tid];
        s *= (1.f/784.f);
        float inv = g3[tid] * rsqrtf(v3[tid] + 1e-5f);
        hsh[tid] = s * inv + (b3[tid] - m3[tid]*inv);
    }
    __syncthreads();
    if (tid < 10) {
        float acc = bc[tid];
        for (int o = 0; o < 64; o++) acc = fmaf(hsh[o], wc[tid*64 + o], acc);
        lg[tid] = acc;
    }
    __syncthreads();
    if (tid < 10) {
        float mx = -1e30f;
        for (int j = 0; j < 10; j++) mx = fmaxf(mx, lg[j]);
        float se = 0.f;
        for (int j = 0; j < 10; j++) se += expf(lg[j] - mx);
        out[b*10 + tid] = lg[tid] - mx - logf(se);
    }
}

// ---------------------------------------------------------------------------
extern "C" void kernel_launch(void* const* d_in, const int* in_sizes, int n_in,
                              void* d_out, int out_size) {
    const float* x  = (const float*)d_in[0];
    const float* w1 = (const float*)d_in[1];
    const float* g1 = (const float*)d_in[2];
    const float* b1 = (const float*)d_in[3];
    const float* m1 = (const float*)d_in[4];
    const float* v1 = (const float*)d_in[5];
    const float* wp = (const float*)d_in[6];
    const float* bp = (const float*)d_in[7];
    const float* w2 = (const float*)d_in[8];
    const float* g2 = (const float*)d_in[9];
    const float* b2 = (const float*)d_in[10];
    const float* m2 = (const float*)d_in[11];
    const float* v2 = (const float*)d_in[12];
    const float* w3 = (const float*)d_in[13];
    const float* g3 = (const float*)d_in[14];
    const float* b3 = (const float*)d_in[15];
    const float* m3 = (const float*)d_in[16];
    const float* v3 = (const float*)d_in[17];
    const float* wc = (const float*)d_in[18];
    const float* bc = (const float*)d_in[19];

    cudaFuncSetAttribute(k2_pconv,  cudaFuncAttributeMaxDynamicSharedMemorySize, 59904);
    cudaFuncSetAttribute(k3_deform, cudaFuncAttributeMaxDynamicSharedMemorySize, 101376);
    cudaFuncSetAttribute(k4_conv3,  cudaFuncAttributeMaxDynamicSharedMemorySize, 96768);

    k1_conv1<<<28800, 256>>>(x, w1, g1, b1, m1, v1);
    k2_pconv<<<BB*7, 128, 59904>>>(wp, bp);
    k3_deform<<<BB*14, 256, 101376>>>(w2, g2, b2, m2, v2);
    k4_conv3<<<BB*7, 128, 96768>>>(w3);
    k5_head<<<BB, 64>>>(g3, b3, m3, v3, wc, bc, (float*)d_out);
}